// round 10
// baseline (speedup 1.0000x reference)
#include <cuda_runtime.h>
#include <cuda_bf16.h>
#include <cstdint>

// Problem constants
#define BSZ   8192
#define D     256
#define H1    50
#define H1S   52              // sH1 row stride (floats)
#define H2    32
#define O     18
#define ROWS  32              // rows per block = MMA M tile
#define NBLK  (BSZ/ROWS)      // 256 blocks -> 2 CTAs/SM coresident
#define TPB   256
#define BS    264             // x smem row stride in bf16 (528B, conflict-free)
#define PBC   (O + 1 + O)     // 37 partial columns

// ---- SMEM byte layout (total 110992 <= 113.5KB for 2 CTAs/SM) ----
#define XHI    0               // 32 x 264 bf16 = 16896
#define XLO    16896           // 16896 (reused post-MMA for H1/H2/WU)
#define WHI    33792           // 256 x 64 bf16 k-major SW128 = 32768
#define WLO    66560           // 32768 (contiguous after WHI)
#define OFF_W2 99328           // 6400
#define OFF_W3 105728          // 2304
#define OFF_B1 108032          // 256
#define OFF_B2 108288          // 128
#define OFF_B3 108416          // 128
#define OFF_Y  108544          // 2304
#define OFF_LD 110848          // 128
#define OFF_FL 110976          // 16
#define SMEM_BYTES 110992
// post-MMA reuse of XLO:
#define OFF_H1 XLO             // 32 x 52 f = 6656
#define OFF_H2 (XLO + 6656)    // 32 x 32 f = 4096
#define OFF_WU (XLO + 10752)   // 32 x 18 f = 2304

// Pre-split, pre-swizzled W1 image: [hi 32KB | lo 32KB] (uint32 words)
__device__ uint32_t g_W1s[2 * 8192];
// Deterministic partial-sum scratch + completion counter
__device__ float g_pB[NBLK][PBC];
__device__ int   g_count = 0;

__device__ __forceinline__ float sigmoidf(float v) {
    return 1.0f / (1.0f + __expf(-v));
}
__device__ __forceinline__ uint32_t smem_u32(const void* p) {
    uint32_t a;
    asm("{ .reg .u64 t; cvta.to.shared.u64 t, %1; cvt.u32.u64 %0, t; }"
        : "=r"(a) : "l"(p));
    return a;
}
// pack hi16(a), hi16(b) into one u32 (lo half = hi16(a))
__device__ __forceinline__ uint32_t prmt7632(uint32_t a, uint32_t b) {
    uint32_t d;
    asm("prmt.b32 %0, %1, %2, 0x7632;" : "=r"(d) : "r"(a), "r"(b));
    return d;
}
__device__ __forceinline__ void split_rn(float v, uint16_t& hi, uint16_t& lo) {
    __nv_bfloat16 h = __float2bfloat16(v);
    float r = v - __bfloat162float(h);
    __nv_bfloat16 l = __float2bfloat16(r);
    hi = *reinterpret_cast<uint16_t*>(&h);
    lo = *reinterpret_cast<uint16_t*>(&l);
}
__device__ __forceinline__ void ldm_x4(uint32_t a[4], uint32_t addr) {
    asm volatile("ldmatrix.sync.aligned.m8n8.x4.shared.b16 {%0,%1,%2,%3}, [%4];"
                 : "=r"(a[0]), "=r"(a[1]), "=r"(a[2]), "=r"(a[3]) : "r"(addr));
}
__device__ __forceinline__ void ldm_x2t(uint32_t b[2], uint32_t addr) {
    asm volatile("ldmatrix.sync.aligned.m8n8.x2.trans.shared.b16 {%0,%1}, [%2];"
                 : "=r"(b[0]), "=r"(b[1]) : "r"(addr));
}
__device__ __forceinline__ void mma_bf16(float c[4], const uint32_t a[4],
                                         const uint32_t b[2]) {
    asm volatile(
        "mma.sync.aligned.m16n8k16.row.col.f32.bf16.bf16.f32 "
        "{%0,%1,%2,%3}, {%4,%5,%6,%7}, {%8,%9}, {%0,%1,%2,%3};"
        : "+f"(c[0]), "+f"(c[1]), "+f"(c[2]), "+f"(c[3])
        : "r"(a[0]), "r"(a[1]), "r"(a[2]), "r"(a[3]), "r"(b[0]), "r"(b[1]));
}

// ---------------------------------------------------------------------------
// Prep kernel: split W1 (rn) into swizzled k-major bf16 hi/lo image (once)
// ---------------------------------------------------------------------------
__global__ void k_prep(const float* __restrict__ W1) {
    const int i = blockIdx.x * 256 + threadIdx.x;   // 8192 u32 slots per image
    const uint32_t k = (uint32_t)i >> 5, u2 = (uint32_t)i & 31;
    uint16_t h0 = 0, l0 = 0, h1_ = 0, l1_ = 0;
    if (u2 < 25) {
        const float2 w = reinterpret_cast<const float2*>(W1)[k * 25 + u2];
        split_rn(w.x, h0, l0);
        split_rn(w.y, h1_, l1_);
    }
    const uint32_t o = (k * 128 + ((u2 * 4) ^ ((k & 7) << 4))) >> 2;
    g_W1s[o]        = (uint32_t)h0 | ((uint32_t)h1_ << 16);
    g_W1s[8192 + o] = (uint32_t)l0 | ((uint32_t)l1_ << 16);
}

// ---------------------------------------------------------------------------
__global__ __launch_bounds__(TPB, 2) void k_main(
    const float* __restrict__ x,  const float* __restrict__ y,
    const float* __restrict__ W1, const float* __restrict__ b1,
    const float* __restrict__ W2, const float* __restrict__ b2,
    const float* __restrict__ W3, const float* __restrict__ b3,
    float* __restrict__ out)
{
    extern __shared__ float sm[];
    char* smb = reinterpret_cast<char*>(sm);
    float* sW2 = reinterpret_cast<float*>(smb + OFF_W2);
    float* sW3 = reinterpret_cast<float*>(smb + OFF_W3);
    float* sb1 = reinterpret_cast<float*>(smb + OFF_B1);
    float* sb2 = reinterpret_cast<float*>(smb + OFF_B2);
    float* sb3 = reinterpret_cast<float*>(smb + OFF_B3);
    float* sH1 = reinterpret_cast<float*>(smb + OFF_H1);
    float* sH2 = reinterpret_cast<float*>(smb + OFF_H2);
    float* sWU = reinterpret_cast<float*>(smb + OFF_WU);
    float* sY  = reinterpret_cast<float*>(smb + OFF_Y);
    float* sLD = reinterpret_cast<float*>(smb + OFF_LD);
    int*   sFlag = reinterpret_cast<int*>(smb + OFF_FL);

    const int tid  = threadIdx.x;
    const int wid  = tid >> 5;
    const int lane = tid & 31;
    const int row0 = blockIdx.x * ROWS;
    const uint32_t sbase = smem_u32(smb);

    // ---- Stage 0a: W1 image copy (pre-split, pre-swizzled) ----
    {
        const uint4* src = reinterpret_cast<const uint4*>(g_W1s);
        uint4* dst = reinterpret_cast<uint4*>(smb + WHI);
#pragma unroll
        for (int i = tid; i < 4096; i += TPB) dst[i] = src[i];
    }
    // ---- Stage 0b: x -> Xhi/Xlo via PRMT truncation split ----
    {
        const float4* xg = reinterpret_cast<const float4*>(x + (size_t)row0 * D);
#pragma unroll
        for (int i = tid; i < ROWS * (D / 4); i += TPB) {
            const uint32_t r = (uint32_t)i >> 6, c4 = (uint32_t)i & 63;
            const float4 v = xg[r * 64 + c4];
            const uint32_t i0 = __float_as_uint(v.x), i1 = __float_as_uint(v.y);
            const uint32_t i2 = __float_as_uint(v.z), i3 = __float_as_uint(v.w);
            const float l0 = v.x - __uint_as_float(i0 & 0xffff0000u);
            const float l1 = v.y - __uint_as_float(i1 & 0xffff0000u);
            const float l2 = v.z - __uint_as_float(i2 & 0xffff0000u);
            const float l3 = v.w - __uint_as_float(i3 & 0xffff0000u);
            const uint32_t byo = (r * BS + c4 * 4) * 2;
            *reinterpret_cast<uint2*>(smb + XHI + byo) =
                make_uint2(prmt7632(i0, i1), prmt7632(i2, i3));
            *reinterpret_cast<uint2*>(smb + XLO + byo) =
                make_uint2(prmt7632(__float_as_uint(l0), __float_as_uint(l1)),
                           prmt7632(__float_as_uint(l2), __float_as_uint(l3)));
        }
    }
    // ---- small tensors ----
    {
        const float2* yg = reinterpret_cast<const float2*>(y + (size_t)row0 * O);
        float2* sYv = reinterpret_cast<float2*>(sY);
        for (int i = tid; i < ROWS * O / 2; i += TPB) sYv[i] = yg[i];
        const float2* W2v = reinterpret_cast<const float2*>(W2);
        float2* sW2v = reinterpret_cast<float2*>(sW2);
        for (int i = tid; i < H1 * H2 / 2; i += TPB) sW2v[i] = W2v[i];
        const float2* W3v = reinterpret_cast<const float2*>(W3);
        float2* sW3v = reinterpret_cast<float2*>(sW3);
        for (int i = tid; i < H2 * O / 2; i += TPB) sW3v[i] = W3v[i];
        if (tid < H1)                 sb1[tid] = b1[tid];
        else if (tid < H1 + H2)       sb2[tid - H1] = b2[tid - H1];
        else if (tid < H1 + H2 + O)   sb3[tid - H1 - H2] = b3[tid - H1 - H2];
    }
    __syncthreads();

    // ---- Layer 1: tensor-core GEMM, warp tile 16m x 16n, 3-term bf16 ----
    float c0[4] = {0.f, 0.f, 0.f, 0.f};
    float c1[4] = {0.f, 0.f, 0.f, 0.f};
    int m0, n0;
    {
        m0 = (wid & 1) * 16;
        n0 = (wid >> 1) * 16;
        const uint32_t arow = m0 + (lane & 15);
        const uint32_t acol = (lane >> 4) * 8;
        const uint32_t aoff = (arow * BS + acol) * 2;
        const uint32_t bl = lane & 15;
        const uint32_t bxor = (bl & 7) << 4;
        uint32_t b0addr = WHI + bl * 128 + ((n0 * 2) ^ bxor);
        uint32_t b1addr = WHI + bl * 128 + (((n0 + 8) * 2) ^ bxor);
        const uint32_t dLO = WLO - WHI;

#pragma unroll
        for (int k0 = 0; k0 < D; k0 += 16) {
            uint32_t ah[4], al[4], bh0[2], bl0[2], bh1[2], bl1[2];
            const uint32_t ka = (uint32_t)k0 * 2;
            ldm_x4(ah, sbase + XHI + aoff + ka);
            ldm_x4(al, sbase + XLO + aoff + ka);
            ldm_x2t(bh0, sbase + b0addr);
            ldm_x2t(bl0, sbase + b0addr + dLO);
            ldm_x2t(bh1, sbase + b1addr);
            ldm_x2t(bl1, sbase + b1addr + dLO);
            mma_bf16(c0, ah, bh0);
            mma_bf16(c1, ah, bh1);
            mma_bf16(c0, ah, bl0);
            mma_bf16(c1, ah, bl1);
            mma_bf16(c0, al, bh0);
            mma_bf16(c1, al, bh1);
            b0addr += 16 * 128;
            b1addr += 16 * 128;
        }
    }
    __syncthreads();   // XLO reads done; reuse as sH1

    // write h1 = sigmoid(acc + b1) from fragments
    {
        const int r0 = m0 + (lane >> 2);
#pragma unroll
        for (int nt = 0; nt < 2; nt++) {
            const int col = n0 + nt * 8 + (lane & 3) * 2;
            if (col < H1) {
                const float bb0 = sb1[col], bb1 = sb1[col + 1];
                const float* c = nt ? c1 : c0;
                *reinterpret_cast<float2*>(sH1 + r0 * H1S + col) =
                    make_float2(sigmoidf(c[0] + bb0), sigmoidf(c[1] + bb1));
                *reinterpret_cast<float2*>(sH1 + (r0 + 8) * H1S + col) =
                    make_float2(sigmoidf(c[2] + bb0), sigmoidf(c[3] + bb1));
            }
        }
    }
    __syncthreads();

    // ---- Layer 2 (32 rows x 32 units, K=50) ----
    {
        const int u  = tid & 31;
        const int rg = tid >> 5;   // 0..7, rows rg + 8*s
        float acc[4];
#pragma unroll
        for (int s = 0; s < 4; s++) acc[s] = sb2[u];
#pragma unroll
        for (int k = 0; k < H1; k += 2) {
            const float w0 = sW2[k * H2 + u];
            const float w1 = sW2[(k + 1) * H2 + u];
#pragma unroll
            for (int s = 0; s < 4; s++) {
                const float2 h = *reinterpret_cast<const float2*>(
                    sH1 + (rg + 8 * s) * H1S + k);
                acc[s] = fmaf(h.x, w0, fmaf(h.y, w1, acc[s]));
            }
        }
#pragma unroll
        for (int s = 0; s < 4; s++)
            sH2[(rg + 8 * s) * H2 + u] = sigmoidf(acc[s]);
    }
    __syncthreads();

    // ---- Layer 3 (32 rows x 18, K=32) -> sWU ----
    {
        const int w = tid >> 5, l = tid & 31;   // 8 warps x 4 rows
        if (l < O) {
#pragma unroll
            for (int rr = 0; rr < 4; rr++) {
                const int r = w * 4 + rr;
                float a = sb3[l];
#pragma unroll
                for (int k = 0; k < H2; k++)
                    a = fmaf(sH2[r * H2 + k], sW3[k * O + l], a);
                sWU[r * O + l] = a;
            }
        }
    }
    __syncthreads();

    // ---- factorized log-denominator per row ----
    if (tid < ROWS) {
        const float* wu = sWU + tid * O;
        float ld = 0.f;
        {
            const float m = fmaxf(wu[0], wu[1]);
            ld += m + __logf(__expf(wu[0] - m) + __expf(wu[1] - m));
        }
        {
            const float m = fmaxf(fmaxf(wu[2], wu[3]), fmaxf(wu[4], wu[5]));
            ld += m + __logf(__expf(wu[2] - m) + __expf(wu[3] - m) +
                             __expf(wu[4] - m) + __expf(wu[5] - m));
        }
        {
            const float m = fmaxf(fmaxf(wu[6], wu[7]), fmaxf(wu[8], wu[9]));
            ld += m + __logf(__expf(wu[6] - m) + __expf(wu[7] - m) +
                             __expf(wu[8] - m) + __expf(wu[9] - m));
        }
        {
            float m = wu[10];
#pragma unroll
            for (int j = 11; j < 18; j++) m = fmaxf(m, wu[j]);
            float s = 0.f;
#pragma unroll
            for (int j = 10; j < 18; j++) s += __expf(wu[j] - m);
            ld += m + __logf(s);
        }
        sLD[tid] = ld;
    }
    __syncthreads();

    // ---- coalesced W_user store ----
    {
        float4* og = reinterpret_cast<float4*>(out + (size_t)row0 * O);
        const float4* wv = reinterpret_cast<const float4*>(sWU);
#pragma unroll
        for (int i = tid; i < ROWS * O / 4; i += TPB) og[i] = wv[i];
    }

    // ---- deterministic block partials (L2-resident) ----
    if (tid < O) {
        float s = 0.f;
#pragma unroll
        for (int r = 0; r < ROWS; r++) s += sWU[r * O + tid];
        __stcg(&g_pB[blockIdx.x][tid], s);
    } else if (tid == O) {
        float s = 0.f;
#pragma unroll
        for (int r = 0; r < ROWS; r++) s += sLD[r];
        __stcg(&g_pB[blockIdx.x][O], s);
    } else if (tid >= 32 && tid < 32 + O) {
        const int j = tid - 32;
        float s = 0.f;
#pragma unroll
        for (int r = 0; r < ROWS; r++) s += sY[r * O + j];
        __stcg(&g_pB[blockIdx.x][O + 1 + j], s);
    }

    // ---- last-block final combine ----
    __threadfence();
    __syncthreads();
    if (tid == 0) {
        const int old = atomicAdd(&g_count, 1);
        *sFlag = (old == NBLK - 1);
    }
    __syncthreads();
    if (!*sFlag) return;
    __threadfence();

    {
        float* part = sm;            // [4][PBC]
        float* tot  = sm + 4 * PBC;  // [PBC]
        const int j   = tid & 63;
        const int seg = tid >> 6;    // 4 segments x 64 blocks
        if (j < PBC) {
            float s = 0.f;
#pragma unroll
            for (int b = 0; b < NBLK / 4; b++)
                s += __ldcg(&g_pB[seg * (NBLK / 4) + b][j]);
            part[seg * PBC + j] = s;
        }
        __syncthreads();
        if (tid < PBC) {
            float s = 0.f;
#pragma unroll
            for (int sg = 0; sg < 4; sg++) s += part[sg * PBC + tid];
            tot[tid] = s;
        }
        __syncthreads();
        if (tid == 0) {
            float dot = 0.f;
#pragma unroll
            for (int jj = 0; jj < O; jj++) dot += tot[jj] * tot[O + 1 + jj];
            out[(size_t)BSZ * O] = -(dot - tot[O]);
            g_count = 0;   // reset for graph replay
        }
    }
}

// ---------------------------------------------------------------------------
extern "C" void kernel_launch(void* const* d_in, const int* in_sizes, int n_in,
                              void* d_out, int out_size) {
    const float* x  = (const float*)d_in[0];
    const float* y  = (const float*)d_in[1];
    const float* W1 = (const float*)d_in[2];
    const float* b1 = (const float*)d_in[3];
    const float* W2 = (const float*)d_in[4];
    const float* b2 = (const float*)d_in[5];
    const float* W3 = (const float*)d_in[6];
    const float* b3 = (const float*)d_in[7];
    float* out = (float*)d_out;

    cudaFuncSetAttribute(k_main, cudaFuncAttributeMaxDynamicSharedMemorySize,
                         SMEM_BYTES);

    k_prep<<<32, 256>>>(W1);
    k_main<<<NBLK, TPB, SMEM_BYTES>>>(x, y, W1, b1, W2, b2, W3, b3, out);
}

// round 11
// speedup vs baseline: 1.1534x; 1.1534x over previous
#include <cuda_runtime.h>
#include <cuda_bf16.h>
#include <cstdint>

// Problem constants
#define BSZ   8192
#define D     256
#define H1    50
#define H1S   52              // sH1 row stride (floats)
#define H2    32
#define O     18
#define ROWS  32              // rows per block = MMA M tile
#define NBLK  (BSZ/ROWS)      // 256 blocks -> 2 CTAs/SM coresident
#define TPB   256
#define BS    264             // x smem row stride in bf16 (528B, conflict-free)
#define PBC   (O + 1 + O)     // 37 partial columns

// ---- SMEM byte layout (total 110992 <= 113.5KB for 2 CTAs/SM) ----
#define XHI    0               // 32 x 264 bf16 = 16896
#define XLO    16896           // 16896 (reused post-MMA for H1/H2/WU)
#define WHI    33792           // 256 x 64 bf16 k-major SW128 = 32768
#define WLO    66560           // 32768 (contiguous after WHI)
#define OFF_W2 99328           // 6400
#define OFF_W3 105728          // 2304
#define OFF_B1 108032          // 256
#define OFF_B2 108288          // 128
#define OFF_B3 108416          // 128
#define OFF_Y  108544          // 2304
#define OFF_LD 110848          // 128
#define OFF_FL 110976          // 16
#define SMEM_BYTES 110992
// post-MMA reuse of XLO:
#define OFF_H1 XLO             // 32 x 52 f = 6656
#define OFF_H2 (XLO + 6656)    // 32 x 32 f = 4096
#define OFF_WU (XLO + 10752)   // 32 x 18 f = 2304

// Deterministic partial-sum scratch + completion counter
__device__ float g_pB[NBLK][PBC];
__device__ int   g_count = 0;

// 1-MUFU sigmoid: EX2 for exp, bit-seed + 2 Newton for the reciprocal.
// rel err ~1.5e-6 (seed 3.3e-2 -> ^4), all division work on the FMA pipe.
__device__ __forceinline__ float fast_sigmoid(float v) {
    const float e = __expf(-v);                  // FMUL + MUFU.EX2
    const float d = 1.0f + e;
    float r = __uint_as_float(0x7EF311C4u - __float_as_uint(d));
    r = r * (2.0f - d * r);
    r = r * (2.0f - d * r);
    return r;
}
__device__ __forceinline__ uint32_t smem_u32(const void* p) {
    uint32_t a;
    asm("{ .reg .u64 t; cvta.to.shared.u64 t, %1; cvt.u32.u64 %0, t; }"
        : "=r"(a) : "l"(p));
    return a;
}
// pack hi16(a), hi16(b) into one u32 (lo half = hi16(a))
__device__ __forceinline__ uint32_t prmt7632(uint32_t a, uint32_t b) {
    uint32_t d;
    asm("prmt.b32 %0, %1, %2, 0x7632;" : "=r"(d) : "r"(a), "r"(b));
    return d;
}
__device__ __forceinline__ void ldm_x4(uint32_t a[4], uint32_t addr) {
    asm volatile("ldmatrix.sync.aligned.m8n8.x4.shared.b16 {%0,%1,%2,%3}, [%4];"
                 : "=r"(a[0]), "=r"(a[1]), "=r"(a[2]), "=r"(a[3]) : "r"(addr));
}
__device__ __forceinline__ void ldm_x2t(uint32_t b[2], uint32_t addr) {
    asm volatile("ldmatrix.sync.aligned.m8n8.x2.trans.shared.b16 {%0,%1}, [%2];"
                 : "=r"(b[0]), "=r"(b[1]) : "r"(addr));
}
__device__ __forceinline__ void mma_bf16(float c[4], const uint32_t a[4],
                                         const uint32_t b[2]) {
    asm volatile(
        "mma.sync.aligned.m16n8k16.row.col.f32.bf16.bf16.f32 "
        "{%0,%1,%2,%3}, {%4,%5,%6,%7}, {%8,%9}, {%0,%1,%2,%3};"
        : "+f"(c[0]), "+f"(c[1]), "+f"(c[2]), "+f"(c[3])
        : "r"(a[0]), "r"(a[1]), "r"(a[2]), "r"(a[3]), "r"(b[0]), "r"(b[1]));
}

// ---------------------------------------------------------------------------
__global__ __launch_bounds__(TPB, 2) void k_main(
    const float* __restrict__ x,  const float* __restrict__ y,
    const float* __restrict__ W1, const float* __restrict__ b1,
    const float* __restrict__ W2, const float* __restrict__ b2,
    const float* __restrict__ W3, const float* __restrict__ b3,
    float* __restrict__ out)
{
    extern __shared__ float sm[];
    char* smb = reinterpret_cast<char*>(sm);
    float* sW2 = reinterpret_cast<float*>(smb + OFF_W2);
    float* sW3 = reinterpret_cast<float*>(smb + OFF_W3);
    float* sb1 = reinterpret_cast<float*>(smb + OFF_B1);
    float* sb2 = reinterpret_cast<float*>(smb + OFF_B2);
    float* sb3 = reinterpret_cast<float*>(smb + OFF_B3);
    float* sH1 = reinterpret_cast<float*>(smb + OFF_H1);
    float* sH2 = reinterpret_cast<float*>(smb + OFF_H2);
    float* sWU = reinterpret_cast<float*>(smb + OFF_WU);
    float* sY  = reinterpret_cast<float*>(smb + OFF_Y);
    float* sLD = reinterpret_cast<float*>(smb + OFF_LD);
    int*   sFlag = reinterpret_cast<int*>(smb + OFF_FL);

    const int tid  = threadIdx.x;
    const int wid  = tid >> 5;
    const int lane = tid & 31;
    const int row0 = blockIdx.x * ROWS;
    const uint32_t sbase = smem_u32(smb);

    // ---- Stage 0a: W1 k-major -> Whi/Wlo via PRMT truncation split ----
    {
        const float2* W1v = reinterpret_cast<const float2*>(W1);
#pragma unroll
        for (int i = tid; i < D * 32; i += TPB) {
            const uint32_t k = (uint32_t)i >> 5, u2 = (uint32_t)i & 31;
            uint32_t hw = 0, lw = 0;
            if (u2 < 25) {
                const float2 w = W1v[k * 25 + u2];
                const uint32_t i0 = __float_as_uint(w.x);
                const uint32_t i1 = __float_as_uint(w.y);
                const float l0 = w.x - __uint_as_float(i0 & 0xffff0000u);
                const float l1 = w.y - __uint_as_float(i1 & 0xffff0000u);
                hw = prmt7632(i0, i1);
                lw = prmt7632(__float_as_uint(l0), __float_as_uint(l1));
            }
            const uint32_t o = k * 128 + ((u2 * 4) ^ ((k & 7) << 4));
            *reinterpret_cast<uint32_t*>(smb + WHI + o) = hw;
            *reinterpret_cast<uint32_t*>(smb + WLO + o) = lw;
        }
    }
    // ---- Stage 0b: x -> Xhi/Xlo via PRMT truncation split ----
    {
        const float4* xg = reinterpret_cast<const float4*>(x + (size_t)row0 * D);
#pragma unroll
        for (int i = tid; i < ROWS * (D / 4); i += TPB) {
            const uint32_t r = (uint32_t)i >> 6, c4 = (uint32_t)i & 63;
            const float4 v = xg[r * 64 + c4];
            const uint32_t i0 = __float_as_uint(v.x), i1 = __float_as_uint(v.y);
            const uint32_t i2 = __float_as_uint(v.z), i3 = __float_as_uint(v.w);
            const float l0 = v.x - __uint_as_float(i0 & 0xffff0000u);
            const float l1 = v.y - __uint_as_float(i1 & 0xffff0000u);
            const float l2 = v.z - __uint_as_float(i2 & 0xffff0000u);
            const float l3 = v.w - __uint_as_float(i3 & 0xffff0000u);
            const uint32_t byo = (r * BS + c4 * 4) * 2;
            *reinterpret_cast<uint2*>(smb + XHI + byo) =
                make_uint2(prmt7632(i0, i1), prmt7632(i2, i3));
            *reinterpret_cast<uint2*>(smb + XLO + byo) =
                make_uint2(prmt7632(__float_as_uint(l0), __float_as_uint(l1)),
                           prmt7632(__float_as_uint(l2), __float_as_uint(l3)));
        }
    }
    // ---- small tensors ----
    {
        const float2* yg = reinterpret_cast<const float2*>(y + (size_t)row0 * O);
        float2* sYv = reinterpret_cast<float2*>(sY);
        for (int i = tid; i < ROWS * O / 2; i += TPB) sYv[i] = yg[i];
        const float2* W2v = reinterpret_cast<const float2*>(W2);
        float2* sW2v = reinterpret_cast<float2*>(sW2);
        for (int i = tid; i < H1 * H2 / 2; i += TPB) sW2v[i] = W2v[i];
        const float2* W3v = reinterpret_cast<const float2*>(W3);
        float2* sW3v = reinterpret_cast<float2*>(sW3);
        for (int i = tid; i < H2 * O / 2; i += TPB) sW3v[i] = W3v[i];
        if (tid < H1)                 sb1[tid] = b1[tid];
        else if (tid < H1 + H2)       sb2[tid - H1] = b2[tid - H1];
        else if (tid < H1 + H2 + O)   sb3[tid - H1 - H2] = b3[tid - H1 - H2];
    }
    __syncthreads();

    // ---- Layer 1: tensor-core GEMM, warp tile 16m x 16n, 3-term bf16 ----
    float c0[4] = {0.f, 0.f, 0.f, 0.f};
    float c1[4] = {0.f, 0.f, 0.f, 0.f};
    int m0, n0;
    {
        m0 = (wid & 1) * 16;
        n0 = (wid >> 1) * 16;
        const uint32_t arow = m0 + (lane & 15);
        const uint32_t acol = (lane >> 4) * 8;
        const uint32_t aoff = (arow * BS + acol) * 2;
        const uint32_t bl = lane & 15;
        const uint32_t bxor = (bl & 7) << 4;
        uint32_t b0addr = WHI + bl * 128 + ((n0 * 2) ^ bxor);
        uint32_t b1addr = WHI + bl * 128 + (((n0 + 8) * 2) ^ bxor);
        const uint32_t dLO = WLO - WHI;

#pragma unroll
        for (int k0 = 0; k0 < D; k0 += 16) {
            uint32_t ah[4], al[4], bh0[2], bl0[2], bh1[2], bl1[2];
            const uint32_t ka = (uint32_t)k0 * 2;
            ldm_x4(ah, sbase + XHI + aoff + ka);
            ldm_x4(al, sbase + XLO + aoff + ka);
            ldm_x2t(bh0, sbase + b0addr);
            ldm_x2t(bl0, sbase + b0addr + dLO);
            ldm_x2t(bh1, sbase + b1addr);
            ldm_x2t(bl1, sbase + b1addr + dLO);
            mma_bf16(c0, ah, bh0);
            mma_bf16(c1, ah, bh1);
            mma_bf16(c0, ah, bl0);
            mma_bf16(c1, ah, bl1);
            mma_bf16(c0, al, bh0);
            mma_bf16(c1, al, bh1);
            b0addr += 16 * 128;
            b1addr += 16 * 128;
        }
    }
    __syncthreads();   // XLO reads done; reuse as sH1

    // write h1 = sigmoid(acc + b1) from fragments
    {
        const int r0 = m0 + (lane >> 2);
#pragma unroll
        for (int nt = 0; nt < 2; nt++) {
            const int col = n0 + nt * 8 + (lane & 3) * 2;
            if (col < H1) {
                const float bb0 = sb1[col], bb1 = sb1[col + 1];
                const float* c = nt ? c1 : c0;
                *reinterpret_cast<float2*>(sH1 + r0 * H1S + col) =
                    make_float2(fast_sigmoid(c[0] + bb0),
                                fast_sigmoid(c[1] + bb1));
                *reinterpret_cast<float2*>(sH1 + (r0 + 8) * H1S + col) =
                    make_float2(fast_sigmoid(c[2] + bb0),
                                fast_sigmoid(c[3] + bb1));
            }
        }
    }
    __syncthreads();

    // ---- Layer 2 (32 rows x 32 units, K=50) ----
    {
        const int u  = tid & 31;
        const int rg = tid >> 5;   // 0..7, rows rg + 8*s
        float acc[4];
#pragma unroll
        for (int s = 0; s < 4; s++) acc[s] = sb2[u];
#pragma unroll
        for (int k = 0; k < H1; k += 2) {
            const float w0 = sW2[k * H2 + u];
            const float w1 = sW2[(k + 1) * H2 + u];
#pragma unroll
            for (int s = 0; s < 4; s++) {
                const float2 h = *reinterpret_cast<const float2*>(
                    sH1 + (rg + 8 * s) * H1S + k);
                acc[s] = fmaf(h.x, w0, fmaf(h.y, w1, acc[s]));
            }
        }
#pragma unroll
        for (int s = 0; s < 4; s++)
            sH2[(rg + 8 * s) * H2 + u] = fast_sigmoid(acc[s]);
    }
    __syncthreads();

    // ---- Layer 3 (32 rows x 18, K=32) -> sWU ----
    {
        const int w = tid >> 5, l = tid & 31;   // 8 warps x 4 rows
        if (l < O) {
#pragma unroll
            for (int rr = 0; rr < 4; rr++) {
                const int r = w * 4 + rr;
                float a = sb3[l];
#pragma unroll
                for (int k = 0; k < H2; k++)
                    a = fmaf(sH2[r * H2 + k], sW3[k * O + l], a);
                sWU[r * O + l] = a;
            }
        }
    }
    __syncthreads();

    // ---- factorized log-denominator per row ----
    if (tid < ROWS) {
        const float* wu = sWU + tid * O;
        float ld = 0.f;
        {
            const float m = fmaxf(wu[0], wu[1]);
            ld += m + __logf(__expf(wu[0] - m) + __expf(wu[1] - m));
        }
        {
            const float m = fmaxf(fmaxf(wu[2], wu[3]), fmaxf(wu[4], wu[5]));
            ld += m + __logf(__expf(wu[2] - m) + __expf(wu[3] - m) +
                             __expf(wu[4] - m) + __expf(wu[5] - m));
        }
        {
            const float m = fmaxf(fmaxf(wu[6], wu[7]), fmaxf(wu[8], wu[9]));
            ld += m + __logf(__expf(wu[6] - m) + __expf(wu[7] - m) +
                             __expf(wu[8] - m) + __expf(wu[9] - m));
        }
        {
            float m = wu[10];
#pragma unroll
            for (int j = 11; j < 18; j++) m = fmaxf(m, wu[j]);
            float s = 0.f;
#pragma unroll
            for (int j = 10; j < 18; j++) s += __expf(wu[j] - m);
            ld += m + __logf(s);
        }
        sLD[tid] = ld;
    }
    __syncthreads();

    // ---- coalesced W_user store ----
    {
        float4* og = reinterpret_cast<float4*>(out + (size_t)row0 * O);
        const float4* wv = reinterpret_cast<const float4*>(sWU);
#pragma unroll
        for (int i = tid; i < ROWS * O / 4; i += TPB) og[i] = wv[i];
    }

    // ---- deterministic block partials (L2-resident) ----
    if (tid < O) {
        float s = 0.f;
#pragma unroll
        for (int r = 0; r < ROWS; r++) s += sWU[r * O + tid];
        __stcg(&g_pB[blockIdx.x][tid], s);
    } else if (tid == O) {
        float s = 0.f;
#pragma unroll
        for (int r = 0; r < ROWS; r++) s += sLD[r];
        __stcg(&g_pB[blockIdx.x][O], s);
    } else if (tid >= 32 && tid < 32 + O) {
        const int j = tid - 32;
        float s = 0.f;
#pragma unroll
        for (int r = 0; r < ROWS; r++) s += sY[r * O + j];
        __stcg(&g_pB[blockIdx.x][O + 1 + j], s);
    }

    // ---- last-block final combine ----
    __threadfence();
    __syncthreads();
    if (tid == 0) {
        const int old = atomicAdd(&g_count, 1);
        *sFlag = (old == NBLK - 1);
    }
    __syncthreads();
    if (!*sFlag) return;
    __threadfence();

    {
        float* part = sm;            // [4][PBC]
        float* tot  = sm + 4 * PBC;  // [PBC]
        const int j   = tid & 63;
        const int seg = tid >> 6;    // 4 segments x 64 blocks
        if (j < PBC) {
            float s = 0.f;
#pragma unroll
            for (int b = 0; b < NBLK / 4; b++)
                s += __ldcg(&g_pB[seg * (NBLK / 4) + b][j]);
            part[seg * PBC + j] = s;
        }
        __syncthreads();
        if (tid < PBC) {
            float s = 0.f;
#pragma unroll
            for (int sg = 0; sg < 4; sg++) s += part[sg * PBC + tid];
            tot[tid] = s;
        }
        __syncthreads();
        if (tid == 0) {
            float dot = 0.f;
#pragma unroll
            for (int jj = 0; jj < O; jj++) dot += tot[jj] * tot[O + 1 + jj];
            out[(size_t)BSZ * O] = -(dot - tot[O]);
            g_count = 0;   // reset for graph replay
        }
    }
}

// ---------------------------------------------------------------------------
extern "C" void kernel_launch(void* const* d_in, const int* in_sizes, int n_in,
                              void* d_out, int out_size) {
    const float* x  = (const float*)d_in[0];
    const float* y  = (const float*)d_in[1];
    const float* W1 = (const float*)d_in[2];
    const float* b1 = (const float*)d_in[3];
    const float* W2 = (const float*)d_in[4];
    const float* b2 = (const float*)d_in[5];
    const float* W3 = (const float*)d_in[6];
    const float* b3 = (const float*)d_in[7];
    float* out = (float*)d_out;

    cudaFuncSetAttribute(k_main, cudaFuncAttributeMaxDynamicSharedMemorySize,
                         SMEM_BYTES);

    k_main<<<NBLK, TPB, SMEM_BYTES>>>(x, y, W1, b1, W2, b2, W3, b3, out);
}